// round 9
// baseline (speedup 1.0000x reference)
#include <cuda_runtime.h>
#include <cstdint>

// ---------------------------------------------------------------------------
// DSS kernel: out[l,h] = Re( sum_n Wk[h,n] * exp(dtLambda[h,n] * l) )
// Fastpath (H=1024, N=64, L=2048): SINGLE fused kernel.
//   FFMA2 measured at rt=4/SMSP -> the only lever is fewer FLOPs/point:
//   * order-4 real recurrence (two n-pairs merged per lane):
//       s_j = a1 s_{j-1} + a2 s_{j-2} + a3 s_{j-3} + a4 s_{j-4}
//     5 packed ops per l-step covering 4 n (vs 6 for the pair scheme).
//   * seed ONCE per full L: the chain runs straight through all 64 steps;
//     acc registers are freed mid-kernel by dumping half-0 to gmem, with
//     per-quad chain state parked in smem across the dump.
//   Block = 128 thr = 4 warps = (2 h) x (2 n-halves); grid = 512.
// ---------------------------------------------------------------------------

#define EPS2 1e-14f   // EPS^2, EPS = 1e-7

#define FH 1024
#define FN 64
#define FL 2048

#define INV_2PI 0.15915494309189535f
#define PI2_HI  6.2831854820251465f
#define PI2_LO  (-1.7484556000744483e-7f)
#define INV2PI_D 0.15915494309189535
#define TWOPI_D  6.283185307179586

typedef unsigned long long u64;
#define PK(d, lo, hi)   asm("mov.b64 %0, {%1, %2};" : "=l"(d) : "f"(lo), "f"(hi))
#define UPK(lo, hi, v)  asm("mov.b64 {%0, %1}, %2;" : "=f"(lo), "=f"(hi) : "l"(v))
#define MUL2(d, a, b)   asm("mul.rn.f32x2 %0, %1, %2;" : "=l"(d) : "l"(a), "l"(b))
#define ADD2(d, a, b)   asm("add.rn.f32x2 %0, %1, %2;" : "=l"(d) : "l"(a), "l"(b))
#define FMA2(d, a, b, c) asm("fma.rn.f32x2 %0, %1, %2, %3;" : "=l"(d) : "l"(a), "l"(b), "l"(c))

// fast sin/cos with explicit Cody-Waite reduction to [-pi, pi]
__device__ __forceinline__ void fast_sincos(float th, float* s, float* c)
{
    float k = rintf(th * INV_2PI);
    float r = fmaf(-k, PI2_HI, th);
    r = fmaf(-k, PI2_LO, r);
    *s = __sinf(r);
    *c = __cosf(r);
}

// precise: reduce mult*b in double, then sincosf on the small residue
__device__ __forceinline__ void dp_sincos(float b, float mult, float* s, float* c)
{
    double th = (double)mult * (double)b;
    double k = rint(th * INV2PI_D);
    float r = (float)(th - k * TWOPI_D);
    sincosf(r, s, c);
}

// ---------------------------------------------------------------------------
// Pair tables per (h_local, np) — float4, parity-packed:
//   t0: (a0, a1, b0, b1)
//   t1: (wkr0, wkr1, nwki0, nwki1)
//   t2: (wki0, wki1, m1r0, m1r1)       m1 = z^32
//   t3: (nm1i0, nm1i1, A1_0, A1_1)     A1 = 2 Re z^32
//   t4: (nB1_0, nB1_1, 0, 0)           B1 = e^{64a}
// Quad tables per (h_local, q):
//   qc0: (a1_0, a1_1, a2_0, a2_1)
//   qc1: (a3_0, a3_1, a4_0, a4_1)
// ---------------------------------------------------------------------------
__global__ void __launch_bounds__(128, 4) k_fused(
    const float* __restrict__ log_dt,
    const float* __restrict__ llnr,
    const float* __restrict__ lim,
    const float* __restrict__ W,
    float* __restrict__ out)
{
    __shared__ float4 npcs[5][2][32];
    __shared__ float4 qc[2][2][16];
    __shared__ u64 qsave[4][8][4][32];     // [warp][quad][k][lane]
    __shared__ float tileA[32][33];
    __shared__ float tileB[32][33];

    const int h0  = blockIdx.x * 2;
    const int tid = threadIdx.x;
    const int w   = tid >> 5;
    const int hl  = w & 1;                  // h_local
    const int nh  = w >> 1;                 // n-half (8 quads each)
    const int p   = tid & 31;

    // ---------------- Phase 1a: per-(h, np) pair constants -------------------
    if (tid < 64) {
        const int hl1 = tid >> 5;
        const int np  = tid & 31;
        const int h   = h0 + hl1;

        float dtr = expf(log_dt[2 * h + 0]);
        float dti = expf(log_dt[2 * h + 1]);

        float a_[2], b_[2], wkr_[2], wki_[2];
        float m1r_[2], nm1i_[2], A1_[2], nB1_[2];

#pragma unroll
        for (int par = 0; par < 2; par++) {
            int n = 2 * np + par;
            float lr = -expf(llnr[n]);
            float li = lim[n];
            float a = dtr * lr;      // < 0
            float b = dti * li;
            a_[par] = a;  b_[par] = b;

            // Wk = Wc * (exp(dtL)-1) * reciprocal_clamped(Lambda)
            float ns = fmaxf(lr * lr + li * li, EPS2);
            float rr =  lr / ns;
            float ri = -li / ns;
            float ea = expf(a), sb, cb;
            sincosf(b, &sb, &cb);
            float edr = ea * cb - 1.0f;
            float edi = ea * sb;
            float wr = W[(h * FN + n) * 2 + 0];
            float wi = W[(h * FN + n) * 2 + 1];
            float tr = wr * edr - wi * edi;
            float ti = wr * edi + wi * edr;
            wkr_[par] = tr * rr - ti * ri;
            wki_[par] = tr * ri + ti * rr;

            // m1 = z^32 (DP-reduced angle)
            float s32, c32;
            dp_sincos(b, 32.0f, &s32, &c32);
            float e32 = expf(32.0f * a);
            float m1r = e32 * c32, m1i = e32 * s32;
            m1r_[par]  = m1r;
            nm1i_[par] = -m1i;

            A1_[par]  = 2.0f * m1r;
            nB1_[par] = -(e32 * e32);        // -e^{64a}
        }

        npcs[0][hl1][np] = make_float4(a_[0], a_[1], b_[0], b_[1]);
        npcs[1][hl1][np] = make_float4(wkr_[0], wkr_[1], -wki_[0], -wki_[1]);
        npcs[2][hl1][np] = make_float4(wki_[0], wki_[1], m1r_[0], m1r_[1]);
        npcs[3][hl1][np] = make_float4(nm1i_[0], nm1i_[1], A1_[0], A1_[1]);
        npcs[4][hl1][np] = make_float4(nB1_[0], nB1_[1], 0.0f, 0.0f);
    }
    __syncthreads();

    // ---------------- Phase 1b: quad (order-4) coefficients ------------------
    // (x^2 - A x + B)(x^2 - A' x + B') ->
    //   s_j = (A+A') s1 - (AA'+B+B') s2 + (AB'+A'B) s3 - (BB') s4
    if (tid < 32) {
        const int hl1 = tid >> 4;
        const int q   = tid & 15;
        float4 p3a = npcs[3][hl1][2 * q];
        float4 p4a = npcs[4][hl1][2 * q];
        float4 p3b = npcs[3][hl1][2 * q + 1];
        float4 p4b = npcs[4][hl1][2 * q + 1];

        float a1_[2], a2_[2], a3_[2], a4_[2];
#pragma unroll
        for (int par = 0; par < 2; par++) {
            float A  = par ? p3a.w : p3a.z;
            float B  = -(par ? p4a.y : p4a.x);
            float Ap = par ? p3b.w : p3b.z;
            float Bp = -(par ? p4b.y : p4b.x);
            a1_[par] = A + Ap;
            a2_[par] = -(A * Ap + B + Bp);
            a3_[par] = A * Bp + Ap * B;
            a4_[par] = -(B * Bp);
        }
        qc[0][hl1][q] = make_float4(a1_[0], a1_[1], a2_[0], a2_[1]);
        qc[1][hl1][q] = make_float4(a3_[0], a3_[1], a4_[0], a4_[1]);
    }
    __syncthreads();

    // ---------------- Phase 2: seeds + order-4 recurrence ---------------------
    const float lm = (float)p - 128.0f;     // G at l = p - 128

    u64 acc[32];
#pragma unroll
    for (int j = 0; j < 32; j++) acc[j] = 0ULL;

    // seed one PAIR: c at l = p-128+32k for k=0..3
    auto seed_pair = [&](int pr, u64& c0, u64& c1, u64& c2, u64& c3) {
        float4 ab = npcs[0][hl][pr];
        ulonglong2 s1v = *reinterpret_cast<const ulonglong2*>(&npcs[1][hl][pr]);
        ulonglong2 s2v = *reinterpret_cast<const ulonglong2*>(&npcs[2][hl][pr]);
        ulonglong2 s3v = *reinterpret_cast<const ulonglong2*>(&npcs[3][hl][pr]);
        ulonglong2 s4v = *reinterpret_cast<const ulonglong2*>(&npcs[4][hl][pr]);

        float e0 = __expf(ab.x * lm);
        float e1 = __expf(ab.y * lm);
        float s0f, c0f, s1f, c1f;
        fast_sincos(ab.z * lm, &s0f, &c0f);
        fast_sincos(ab.w * lm, &s1f, &c1f);
        u64 Er2, Ei2;
        PK(Er2, e0 * c0f, e1 * c1f);
        PK(Ei2, e0 * s0f, e1 * s1f);

        u64 Gr, Gi, t;
        MUL2(t, s1v.x, Er2);  FMA2(Gr, s1v.y, Ei2, t);   // wkr*Er - wki*Ei
        MUL2(t, s1v.x, Ei2);  FMA2(Gi, s2v.x, Er2, t);   // wkr*Ei + wki*Er

        c0 = Gr;                                          // l = p-128
        MUL2(t, s2v.y, Gr);   FMA2(c1, s3v.x, Gi, t);     // Re(G*m1): l = p-96
        MUL2(t, s3v.y, c1);   FMA2(c2, s4v.x, c0, t);     // l = p-64
        MUL2(t, s3v.y, c2);   FMA2(c3, s4v.x, c1, t);     // l = p-32
    };

    const int q0 = nh * 8;

    // ---- half 0: seed + 32 steps, park state ----
#pragma unroll 1
    for (int qq = 0; qq < 8; qq++) {
        int q = q0 + qq;
        u64 cA0, cA1, cA2, cA3, cB0, cB1, cB2, cB3;
        seed_pair(2 * q,     cA0, cA1, cA2, cA3);
        seed_pair(2 * q + 1, cB0, cB1, cB2, cB3);
        u64 h1, h2, h3, h4;
        ADD2(h1, cA3, cB3);   // l = p-32
        ADD2(h2, cA2, cB2);   // l = p-64
        ADD2(h3, cA1, cB1);   // l = p-96
        ADD2(h4, cA0, cB0);   // l = p-128

        ulonglong2 q12 = *reinterpret_cast<const ulonglong2*>(&qc[0][hl][q]);
        ulonglong2 q34 = *reinterpret_cast<const ulonglong2*>(&qc[1][hl][q]);

#pragma unroll
        for (int j = 0; j < 32; j++) {
            u64 t;
            MUL2(t, q34.y, h4);
            FMA2(t, q34.x, h3, t);
            FMA2(t, q12.y, h2, t);
            FMA2(t, q12.x, h1, t);            // value at l = p + 32j
            ADD2(acc[j], acc[j], t);
            h4 = h3;  h3 = h2;  h2 = h1;  h1 = t;
        }
        qsave[w][qq][0][p] = h1;
        qsave[w][qq][1][p] = h2;
        qsave[w][qq][2][p] = h3;
        qsave[w][qq][3][p] = h4;
    }

    // ---- dump half 0 ----
    {
        float (*tile)[33] = hl ? tileB : tileA;
        if (nh == 0) {
#pragma unroll
            for (int j = 0; j < 32; j++) {
                float lo, hi;
                UPK(lo, hi, acc[j]);
                tile[j][p] = lo + hi;
            }
        }
        __syncthreads();
        if (nh == 1) {
#pragma unroll
            for (int j = 0; j < 32; j++) {
                float lo, hi;
                UPK(lo, hi, acc[j]);
                tile[j][p] += lo + hi;
            }
        }
        __syncthreads();
        const int kk = tid >> 5;
        const int pp = tid & 31;
#pragma unroll
        for (int k = kk; k < 32; k += 4) {
            float2 v = make_float2(tileA[k][pp], tileB[k][pp]);
            *reinterpret_cast<float2*>(out + (size_t)((k << 5) + pp) * FH + h0) = v;
        }
        __syncthreads();
    }

#pragma unroll
    for (int j = 0; j < 32; j++) acc[j] = 0ULL;

    // ---- half 1: resume chains, 32 more steps ----
#pragma unroll 1
    for (int qq = 0; qq < 8; qq++) {
        int q = q0 + qq;
        u64 h1 = qsave[w][qq][0][p];
        u64 h2 = qsave[w][qq][1][p];
        u64 h3 = qsave[w][qq][2][p];
        u64 h4 = qsave[w][qq][3][p];

        ulonglong2 q12 = *reinterpret_cast<const ulonglong2*>(&qc[0][hl][q]);
        ulonglong2 q34 = *reinterpret_cast<const ulonglong2*>(&qc[1][hl][q]);

#pragma unroll
        for (int j = 0; j < 32; j++) {
            u64 t;
            MUL2(t, q34.y, h4);
            FMA2(t, q34.x, h3, t);
            FMA2(t, q12.y, h2, t);
            FMA2(t, q12.x, h1, t);            // value at l = 1024 + p + 32j
            ADD2(acc[j], acc[j], t);
            h4 = h3;  h3 = h2;  h2 = h1;  h1 = t;
        }
    }

    // ---- dump half 1 ----
    {
        float (*tile)[33] = hl ? tileB : tileA;
        if (nh == 0) {
#pragma unroll
            for (int j = 0; j < 32; j++) {
                float lo, hi;
                UPK(lo, hi, acc[j]);
                tile[j][p] = lo + hi;
            }
        }
        __syncthreads();
        if (nh == 1) {
#pragma unroll
            for (int j = 0; j < 32; j++) {
                float lo, hi;
                UPK(lo, hi, acc[j]);
                tile[j][p] += lo + hi;
            }
        }
        __syncthreads();
        const int kk = tid >> 5;
        const int pp = tid & 31;
#pragma unroll
        for (int k = kk; k < 32; k += 4) {
            float2 v = make_float2(tileA[k][pp], tileB[k][pp]);
            *reinterpret_cast<float2*>(out + (size_t)(1024 + (k << 5) + pp) * FH + h0) = v;
        }
    }
}

// ---------------------------------------------------------------------------
// Generic fallback (correct for any shape; slow).
// ---------------------------------------------------------------------------
__global__ void k_generic(const float* __restrict__ log_dt,
                          const float* __restrict__ llnr,
                          const float* __restrict__ lim,
                          const float* __restrict__ W,
                          float* __restrict__ out,
                          int H, int N, int L)
{
    int idx = blockIdx.x * blockDim.x + threadIdx.x;
    if (idx >= L * H) return;
    int l = idx / H, h = idx - l * H;
    float dtr = expf(log_dt[2 * h + 0]);
    float dti = expf(log_dt[2 * h + 1]);
    float fl = (float)l;
    float sum = 0.0f;
    for (int n = 0; n < N; n++) {
        float lr = -expf(llnr[n]);
        float li = lim[n];
        float a = dtr * lr, b = dti * li;
        float ns = fmaxf(lr * lr + li * li, EPS2);
        float rr = lr / ns, ri = -li / ns;
        float ea = expf(a), sb, cb;
        sincosf(b, &sb, &cb);
        float edr = ea * cb - 1.0f, edi = ea * sb;
        float wr = W[(h * N + n) * 2 + 0], wi = W[(h * N + n) * 2 + 1];
        float tr = wr * edr - wi * edi, ti = wr * edi + wi * edr;
        float wkr = tr * rr - ti * ri, wki = tr * ri + ti * rr;
        float el = expf(a * fl), sl, cl;
        sincosf(b * fl, &sl, &cl);
        sum += wkr * (el * cl) - wki * (el * sl);
    }
    out[idx] = sum;
}

// ---------------------------------------------------------------------------
extern "C" void kernel_launch(void* const* d_in, const int* in_sizes, int n_in,
                              void* d_out, int out_size)
{
    const float* log_dt = (const float*)d_in[0];   // (H,2)
    const float* llnr   = (const float*)d_in[1];   // (N,)
    const float* lim    = (const float*)d_in[2];   // (N,)
    const float* W      = (const float*)d_in[3];   // (H,N,2)
    float* out = (float*)d_out;

    int H = in_sizes[0] / 2;
    int N = in_sizes[1];
    int L = out_size / H;

    if (H == FH && N == FN && L == FL) {
        k_fused<<<FH / 2, 128>>>(log_dt, llnr, lim, W, out);
    } else {
        int tot = L * H;
        k_generic<<<(tot + 255) / 256, 256>>>(log_dt, llnr, lim, W, out, H, N, L);
    }
}